// round 1
// baseline (speedup 1.0000x reference)
#include <cuda_runtime.h>

#define DD 160
#define HH 192
#define WW 160
#define DHW (DD*HH*WW)

__device__ __forceinline__ float sample1(const float* __restrict__ v,
                                         float ix, float iy, float iz) {
    // fully out-of-bounds -> exact zero
    if (ix <= -1.0f || ix >= (float)WW ||
        iy <= -1.0f || iy >= (float)HH ||
        iz <= -1.0f || iz >= (float)DD) return 0.0f;
    float x0f = floorf(ix), y0f = floorf(iy), z0f = floorf(iz);
    int x0 = (int)x0f, y0 = (int)y0f, z0 = (int)z0f;
    float tx = ix - x0f, ty = iy - y0f, tz = iz - z0f;
    float acc = 0.0f;
    #pragma unroll
    for (int dz = 0; dz < 2; dz++) {
        int zc = z0 + dz;
        if ((unsigned)zc >= (unsigned)DD) continue;
        float wz = dz ? tz : 1.0f - tz;
        #pragma unroll
        for (int dy = 0; dy < 2; dy++) {
            int yc = y0 + dy;
            if ((unsigned)yc >= (unsigned)HH) continue;
            float wy = dy ? ty : 1.0f - ty;
            float wzy = wz * wy;
            long base = ((long)zc * HH + yc) * WW;
            #pragma unroll
            for (int dx = 0; dx < 2; dx++) {
                int xc = x0 + dx;
                if ((unsigned)xc >= (unsigned)WW) continue;
                float w = wzy * (dx ? tx : 1.0f - tx);
                acc = fmaf(w, __ldg(v + base + xc), acc);
            }
        }
    }
    return acc;
}

__device__ __forceinline__ void sample3(const float* __restrict__ v,
                                        float ix, float iy, float iz,
                                        float& o0, float& o1, float& o2) {
    o0 = 0.0f; o1 = 0.0f; o2 = 0.0f;
    // dominant path: grid2 coords are unnormalized voxel coords fed into a
    // normalized-coordinate sampler -> almost always fully out of bounds.
    if (ix <= -1.0f || ix >= (float)WW ||
        iy <= -1.0f || iy >= (float)HH ||
        iz <= -1.0f || iz >= (float)DD) return;
    float x0f = floorf(ix), y0f = floorf(iy), z0f = floorf(iz);
    int x0 = (int)x0f, y0 = (int)y0f, z0 = (int)z0f;
    float tx = ix - x0f, ty = iy - y0f, tz = iz - z0f;
    #pragma unroll
    for (int dz = 0; dz < 2; dz++) {
        int zc = z0 + dz;
        if ((unsigned)zc >= (unsigned)DD) continue;
        float wz = dz ? tz : 1.0f - tz;
        #pragma unroll
        for (int dy = 0; dy < 2; dy++) {
            int yc = y0 + dy;
            if ((unsigned)yc >= (unsigned)HH) continue;
            float wy = dy ? ty : 1.0f - ty;
            float wzy = wz * wy;
            long base = ((long)zc * HH + yc) * WW;
            #pragma unroll
            for (int dx = 0; dx < 2; dx++) {
                int xc = x0 + dx;
                if ((unsigned)xc >= (unsigned)WW) continue;
                float w = wzy * (dx ? tx : 1.0f - tx);
                long off = base + xc;
                o0 = fmaf(w, __ldg(v + off), o0);
                o1 = fmaf(w, __ldg(v + DHW + off), o1);
                o2 = fmaf(w, __ldg(v + 2L*DHW + off), o2);
            }
        }
    }
}

__global__ void st_kernel(const float* __restrict__ src,
                          const float* __restrict__ flow1,
                          const float* __restrict__ flow2,
                          const float* __restrict__ rf_p,
                          float* __restrict__ out) {
    int idx = blockIdx.x * blockDim.x + threadIdx.x;
    if (idx >= DHW) return;

    int x = idx % WW;
    int t = idx / WW;
    int y = t % HH;
    int z = t / HH;

    float rf = __ldg(rf_p);

    // flow2 channels: ch0 = z-dir, ch1 = y-dir, ch2 = x-dir (match grid channels)
    float f2z = __ldg(flow2 + idx);
    float f2y = __ldg(flow2 + DHW + idx);
    float f2x = __ldg(flow2 + 2L*DHW + idx);

    // grid2 = grid + flow2 * rf  (grid is analytic meshgrid)
    float g2z = (float)z + f2z * rf;
    float g2y = (float)y + f2y * rf;
    float g2x = (float)x + f2x * rf;

    // grid_sample(flow1, grid2): unnorm applied to raw voxel coords
    // ix = ((c + 1) * s - 1) * 0.5   (align_corners=False)
    float ix = ((g2x + 1.0f) * (float)WW - 1.0f) * 0.5f;
    float iy = ((g2y + 1.0f) * (float)HH - 1.0f) * 0.5f;
    float iz = ((g2z + 1.0f) * (float)DD - 1.0f) * 0.5f;

    float w0, w1, w2;
    sample3(flow1, ix, iy, iz, w0, w1, w2);

    // out_flow = flow1_warped + flow2
    float oz = w0 + f2z;
    float oy = w1 + f2y;
    float ox = w2 + f2x;

    // new_locs_total = grid + out_flow*rf, normalized by (dim-1), then unnorm
    float vz = (float)z + oz * rf;
    float vy = (float)y + oy * rf;
    float vx = (float)x + ox * rf;

    float nz = 2.0f * (vz / (float)(DD - 1) - 0.5f);
    float ny = 2.0f * (vy / (float)(HH - 1) - 0.5f);
    float nx = 2.0f * (vx / (float)(WW - 1) - 0.5f);

    float sx = ((nx + 1.0f) * (float)WW - 1.0f) * 0.5f;
    float sy = ((ny + 1.0f) * (float)HH - 1.0f) * 0.5f;
    float sz = ((nz + 1.0f) * (float)DD - 1.0f) * 0.5f;

    float img = sample1(src, sx, sy, sz);

    // output layout: [deform_2_img (DHW) | out_flow (3*DHW)]
    out[idx] = img;
    out[DHW + idx] = oz;
    out[2L*DHW + idx] = oy;
    out[3L*DHW + idx] = ox;
}

extern "C" void kernel_launch(void* const* d_in, const int* in_sizes, int n_in,
                              void* d_out, int out_size) {
    const float* src   = (const float*)d_in[0];
    const float* flow1 = (const float*)d_in[1];
    const float* flow2 = (const float*)d_in[2];
    // d_in[3] is the meshgrid — analytic, not loaded
    const float* rf    = (const float*)d_in[4];
    float* out = (float*)d_out;

    int threads = 256;
    int blocks = (DHW + threads - 1) / threads;
    st_kernel<<<blocks, threads>>>(src, flow1, flow2, rf, out);
}

// round 4
// speedup vs baseline: 1.3243x; 1.3243x over previous
#include <cuda_runtime.h>

#define DD 160
#define HH 192
#define WW 160
#define DHW (DD*HH*WW)
#define VEC 4

__device__ __forceinline__ float sample1(const float* __restrict__ v,
                                         float ix, float iy, float iz) {
    if (ix <= -1.0f || ix >= (float)WW ||
        iy <= -1.0f || iy >= (float)HH ||
        iz <= -1.0f || iz >= (float)DD) return 0.0f;
    float x0f = floorf(ix), y0f = floorf(iy), z0f = floorf(iz);
    int x0 = (int)x0f, y0 = (int)y0f, z0 = (int)z0f;
    float tx = ix - x0f, ty = iy - y0f, tz = iz - z0f;
    float acc = 0.0f;
    #pragma unroll
    for (int dz = 0; dz < 2; dz++) {
        int zc = z0 + dz;
        if ((unsigned)zc >= (unsigned)DD) continue;
        float wz = dz ? tz : 1.0f - tz;
        #pragma unroll
        for (int dy = 0; dy < 2; dy++) {
            int yc = y0 + dy;
            if ((unsigned)yc >= (unsigned)HH) continue;
            float wy = dy ? ty : 1.0f - ty;
            float wzy = wz * wy;
            unsigned base = ((unsigned)zc * HH + (unsigned)yc) * WW;
            #pragma unroll
            for (int dx = 0; dx < 2; dx++) {
                int xc = x0 + dx;
                if ((unsigned)xc >= (unsigned)WW) continue;
                float w = wzy * (dx ? tx : 1.0f - tx);
                acc = fmaf(w, __ldg(v + base + (unsigned)xc), acc);
            }
        }
    }
    return acc;
}

__device__ __forceinline__ void sample3(const float* __restrict__ v,
                                        float ix, float iy, float iz,
                                        float& o0, float& o1, float& o2) {
    o0 = 0.0f; o1 = 0.0f; o2 = 0.0f;
    if (ix <= -1.0f || ix >= (float)WW ||
        iy <= -1.0f || iy >= (float)HH ||
        iz <= -1.0f || iz >= (float)DD) return;
    float x0f = floorf(ix), y0f = floorf(iy), z0f = floorf(iz);
    int x0 = (int)x0f, y0 = (int)y0f, z0 = (int)z0f;
    float tx = ix - x0f, ty = iy - y0f, tz = iz - z0f;
    #pragma unroll
    for (int dz = 0; dz < 2; dz++) {
        int zc = z0 + dz;
        if ((unsigned)zc >= (unsigned)DD) continue;
        float wz = dz ? tz : 1.0f - tz;
        #pragma unroll
        for (int dy = 0; dy < 2; dy++) {
            int yc = y0 + dy;
            if ((unsigned)yc >= (unsigned)HH) continue;
            float wy = dy ? ty : 1.0f - ty;
            float wzy = wz * wy;
            unsigned base = ((unsigned)zc * HH + (unsigned)yc) * WW;
            #pragma unroll
            for (int dx = 0; dx < 2; dx++) {
                int xc = x0 + dx;
                if ((unsigned)xc >= (unsigned)WW) continue;
                float w = wzy * (dx ? tx : 1.0f - tx);
                unsigned off = base + (unsigned)xc;
                o0 = fmaf(w, __ldg(v + off), o0);
                o1 = fmaf(w, __ldg(v + DHW + off), o1);
                o2 = fmaf(w, __ldg(v + 2u*DHW + off), o2);
            }
        }
    }
}

__global__ void __launch_bounds__(256) st_kernel(
                          const float* __restrict__ src,
                          const float* __restrict__ flow1,
                          const float* __restrict__ flow2,
                          const float* __restrict__ rf_p,
                          float* __restrict__ out) {
    unsigned tid = blockIdx.x * blockDim.x + threadIdx.x;
    unsigned idx = tid * VEC;
    if (idx >= DHW) return;

    // WW % VEC == 0 so all VEC voxels share (z, y)
    unsigned xb = idx % WW;
    unsigned t  = idx / WW;
    unsigned y  = t % HH;
    unsigned z  = t / HH;

    float rf = __ldg(rf_p);

    const float4 f2z4 = *(const float4*)(flow2 + idx);
    const float4 f2y4 = *(const float4*)(flow2 + DHW + idx);
    const float4 f2x4 = *(const float4*)(flow2 + 2u*DHW + idx);

    float img[VEC], oz[VEC], oy[VEC], ox[VEC];
    const float* f2z = (const float*)&f2z4;
    const float* f2y = (const float*)&f2y4;
    const float* f2x = (const float*)&f2x4;

    #pragma unroll
    for (int j = 0; j < VEC; j++) {
        float x = (float)(xb + j);
        float yf = (float)y, zf = (float)z;

        // grid2 = grid + flow2 * rf  (grid analytic)
        float g2z = zf + f2z[j] * rf;
        float g2y = yf + f2y[j] * rf;
        float g2x = x  + f2x[j] * rf;

        // grid_sample(flow1, grid2) coord unnorm (align_corners=False)
        float ix = ((g2x + 1.0f) * (float)WW - 1.0f) * 0.5f;
        float iy = ((g2y + 1.0f) * (float)HH - 1.0f) * 0.5f;
        float iz = ((g2z + 1.0f) * (float)DD - 1.0f) * 0.5f;

        float w0, w1, w2;
        sample3(flow1, ix, iy, iz, w0, w1, w2);

        // out_flow = flow1_warped + flow2
        oz[j] = w0 + f2z[j];
        oy[j] = w1 + f2y[j];
        ox[j] = w2 + f2x[j];

        // new_locs_total = grid + out_flow*rf -> normalize -> unnorm
        float vz = zf + oz[j] * rf;
        float vy = yf + oy[j] * rf;
        float vx = x  + ox[j] * rf;

        float nz = 2.0f * (vz / (float)(DD - 1) - 0.5f);
        float ny = 2.0f * (vy / (float)(HH - 1) - 0.5f);
        float nx = 2.0f * (vx / (float)(WW - 1) - 0.5f);

        float sx = ((nx + 1.0f) * (float)WW - 1.0f) * 0.5f;
        float sy = ((ny + 1.0f) * (float)HH - 1.0f) * 0.5f;
        float sz = ((nz + 1.0f) * (float)DD - 1.0f) * 0.5f;

        img[j] = sample1(src, sx, sy, sz);
    }

    *(float4*)(out + idx)          = *(float4*)img;
    *(float4*)(out + DHW + idx)    = *(float4*)oz;
    *(float4*)(out + 2u*DHW + idx) = *(float4*)oy;
    *(float4*)(out + 3u*DHW + idx) = *(float4*)ox;
}

extern "C" void kernel_launch(void* const* d_in, const int* in_sizes, int n_in,
                              void* d_out, int out_size) {
    const float* src   = (const float*)d_in[0];
    const float* flow1 = (const float*)d_in[1];
    const float* flow2 = (const float*)d_in[2];
    // d_in[3] meshgrid — analytic, not loaded
    const float* rf    = (const float*)d_in[4];
    float* out = (float*)d_out;

    int threads = 256;
    int total = DHW / VEC;
    int blocks = (total + threads - 1) / threads;
    st_kernel<<<blocks, threads>>>(src, flow1, flow2, rf, out);
}

// round 5
// speedup vs baseline: 1.7561x; 1.3261x over previous
#include <cuda_runtime.h>

#define DD 160
#define HH 192
#define WW 160
#define DHW (DD*HH*WW)

__device__ __forceinline__ float sample1(const float* __restrict__ v,
                                         float ix, float iy, float iz) {
    if (ix <= -1.0f || ix >= (float)WW ||
        iy <= -1.0f || iy >= (float)HH ||
        iz <= -1.0f || iz >= (float)DD) return 0.0f;
    float x0f = floorf(ix), y0f = floorf(iy), z0f = floorf(iz);
    int x0 = (int)x0f, y0 = (int)y0f, z0 = (int)z0f;
    float tx = ix - x0f, ty = iy - y0f, tz = iz - z0f;
    // gather all 8 corners first (max MLP), then accumulate
    float val[8];
    float wgt[8];
    #pragma unroll
    for (int c = 0; c < 8; c++) {
        int dz = (c >> 2) & 1, dy = (c >> 1) & 1, dx = c & 1;
        int zc = z0 + dz, yc = y0 + dy, xc = x0 + dx;
        bool inb = ((unsigned)zc < (unsigned)DD) &
                   ((unsigned)yc < (unsigned)HH) &
                   ((unsigned)xc < (unsigned)WW);
        unsigned zi = (unsigned)min(max(zc, 0), DD - 1);
        unsigned yi = (unsigned)min(max(yc, 0), HH - 1);
        unsigned xi = (unsigned)min(max(xc, 0), WW - 1);
        val[c] = __ldg(v + (zi * HH + yi) * WW + xi);
        float w = (dz ? tz : 1.0f - tz) * (dy ? ty : 1.0f - ty)
                * (dx ? tx : 1.0f - tx);
        wgt[c] = inb ? w : 0.0f;
    }
    float acc = 0.0f;
    #pragma unroll
    for (int c = 0; c < 8; c++) acc = fmaf(wgt[c], val[c], acc);
    return acc;
}

__device__ __forceinline__ void sample3(const float* __restrict__ v,
                                        float ix, float iy, float iz,
                                        float& o0, float& o1, float& o2) {
    o0 = 0.0f; o1 = 0.0f; o2 = 0.0f;
    // practically always fully out of bounds (unnormalized coords fed to
    // a normalized-coordinate sampler) -> warp-uniform early-out
    if (ix <= -1.0f || ix >= (float)WW ||
        iy <= -1.0f || iy >= (float)HH ||
        iz <= -1.0f || iz >= (float)DD) return;
    float x0f = floorf(ix), y0f = floorf(iy), z0f = floorf(iz);
    int x0 = (int)x0f, y0 = (int)y0f, z0 = (int)z0f;
    float tx = ix - x0f, ty = iy - y0f, tz = iz - z0f;
    #pragma unroll
    for (int dz = 0; dz < 2; dz++) {
        int zc = z0 + dz;
        if ((unsigned)zc >= (unsigned)DD) continue;
        float wz = dz ? tz : 1.0f - tz;
        #pragma unroll
        for (int dy = 0; dy < 2; dy++) {
            int yc = y0 + dy;
            if ((unsigned)yc >= (unsigned)HH) continue;
            float wy = dy ? ty : 1.0f - ty;
            float wzy = wz * wy;
            unsigned base = ((unsigned)zc * HH + (unsigned)yc) * WW;
            #pragma unroll
            for (int dx = 0; dx < 2; dx++) {
                int xc = x0 + dx;
                if ((unsigned)xc >= (unsigned)WW) continue;
                float w = wzy * (dx ? tx : 1.0f - tx);
                unsigned off = base + (unsigned)xc;
                o0 = fmaf(w, __ldg(v + off), o0);
                o1 = fmaf(w, __ldg(v + DHW + off), o1);
                o2 = fmaf(w, __ldg(v + 2u*DHW + off), o2);
            }
        }
    }
}

// block (32,8): warp = 32 stride-1 x at one (y,z); thread unrolls 4 consecutive y
__global__ void __launch_bounds__(256) st_kernel(
                          const float* __restrict__ src,
                          const float* __restrict__ flow1,
                          const float* __restrict__ flow2,
                          const float* __restrict__ rf_p,
                          float* __restrict__ out) {
    unsigned x  = blockIdx.x * 32u + threadIdx.x;
    unsigned z  = blockIdx.z;
    unsigned yb = blockIdx.y * 32u + threadIdx.y * 4u;

    float rf = __ldg(rf_p);
    float xf = (float)x, zf = (float)z;

    unsigned idx0 = (z * HH + yb) * WW + x;

    // front-batched flow2 loads (MLP = 12)
    float f2z[4], f2y[4], f2x[4];
    #pragma unroll
    for (int j = 0; j < 4; j++) {
        unsigned idx = idx0 + j * WW;
        f2z[j] = __ldg(flow2 + idx);
        f2y[j] = __ldg(flow2 + DHW + idx);
        f2x[j] = __ldg(flow2 + 2u*DHW + idx);
    }

    #pragma unroll
    for (int j = 0; j < 4; j++) {
        unsigned idx = idx0 + j * WW;
        float yf = (float)(yb + j);

        // grid2 = grid + flow2 * rf  (grid analytic)
        float g2z = zf + f2z[j] * rf;
        float g2y = yf + f2y[j] * rf;
        float g2x = xf + f2x[j] * rf;

        // grid_sample(flow1, grid2) coord unnorm (align_corners=False)
        float ix = ((g2x + 1.0f) * (float)WW - 1.0f) * 0.5f;
        float iy = ((g2y + 1.0f) * (float)HH - 1.0f) * 0.5f;
        float iz = ((g2z + 1.0f) * (float)DD - 1.0f) * 0.5f;

        float w0, w1, w2;
        sample3(flow1, ix, iy, iz, w0, w1, w2);

        // out_flow = flow1_warped + flow2
        float oz = w0 + f2z[j];
        float oy = w1 + f2y[j];
        float ox = w2 + f2x[j];

        // new_locs_total = grid + out_flow*rf -> normalize -> unnorm
        float vz = zf + oz * rf;
        float vy = yf + oy * rf;
        float vx = xf + ox * rf;

        float nz = 2.0f * (vz / (float)(DD - 1) - 0.5f);
        float ny = 2.0f * (vy / (float)(HH - 1) - 0.5f);
        float nx = 2.0f * (vx / (float)(WW - 1) - 0.5f);

        float sx = ((nx + 1.0f) * (float)WW - 1.0f) * 0.5f;
        float sy = ((ny + 1.0f) * (float)HH - 1.0f) * 0.5f;
        float sz = ((nz + 1.0f) * (float)DD - 1.0f) * 0.5f;

        float img = sample1(src, sx, sy, sz);

        out[idx]            = img;
        out[DHW + idx]      = oz;
        out[2u*DHW + idx]   = oy;
        out[3u*DHW + idx]   = ox;
    }
}

extern "C" void kernel_launch(void* const* d_in, const int* in_sizes, int n_in,
                              void* d_out, int out_size) {
    const float* src   = (const float*)d_in[0];
    const float* flow1 = (const float*)d_in[1];
    const float* flow2 = (const float*)d_in[2];
    // d_in[3] meshgrid — analytic, not loaded
    const float* rf    = (const float*)d_in[4];
    float* out = (float*)d_out;

    dim3 block(32, 8);
    dim3 grid(WW / 32, HH / 32, DD);
    st_kernel<<<grid, block>>>(src, flow1, flow2, rf, out);
}